// round 3
// baseline (speedup 1.0000x reference)
#include <cuda_runtime.h>
#include <math.h>

// Sinkhorn distance, N=M=4096, D=256, EPS=0.1, 100 iterations.
// Persistent single-wave kernel: fused u+v update per iteration, C read once.
// All values pre-scaled by LOG2E/EPS so inner loops use exp2/log2 (MUFU).

#define NN 4096
#define KK 256
#define SCALEF 14.4269504088896340736f   // log2(e)/EPS
#define NEG_BIG (-1e30f)
#define THREADS 512
#define NBMAX 160
#define N_ITER 100

// ---- device scratch (no runtime allocations allowed) ----
__device__ __align__(16) float g_C2[(size_t)NN * NN];     // 64 MB: C * SCALEF
__device__ __align__(16) float g_u[NN];
__device__ __align__(16) float g_v[NN];
__device__ float g_xs[NN];
__device__ float g_ys[NN];
__device__ __align__(16) float g_MP[(size_t)NBMAX * NN];  // per-CTA column max partials
__device__ __align__(16) float g_SP[(size_t)NBMAX * NN];  // per-CTA column sum partials
__device__ double g_dpart[NBMAX];

// ---- software grid barrier state ----
__device__ unsigned g_bar_count;
__device__ volatile unsigned g_bar_gen;

__device__ __forceinline__ float ex2f(float x) {
    float r; asm("ex2.approx.ftz.f32 %0, %1;" : "=f"(r) : "f"(x)); return r;
}
__device__ __forceinline__ float lg2f(float x) {
    float r; asm("lg2.approx.ftz.f32 %0, %1;" : "=f"(r) : "f"(x)); return r;
}

__device__ __forceinline__ void grid_sync(int NB) {
    __syncthreads();
    if (threadIdx.x == 0) {
        unsigned gen = g_bar_gen;
        __threadfence();
        unsigned t = atomicAdd(&g_bar_count, 1u);
        if (t == (unsigned)(NB - 1)) {
            g_bar_count = 0;
            __threadfence();
            g_bar_gen = gen + 1;
        } else {
            while (g_bar_gen == gen) { }
        }
        __threadfence();
    }
    __syncthreads();
}

// ---------------------------------------------------------------------------
// squared row norms of x and y. global warp w handles one row.
__global__ __launch_bounds__(256) void sqnorm_kernel(const float* __restrict__ X,
                                                     const float* __restrict__ Y) {
    int gw = (blockIdx.x * 256 + threadIdx.x) >> 5;
    int lane = threadIdx.x & 31;
    const float* src = (gw < NN) ? (X + (size_t)gw * KK) : (Y + (size_t)(gw - NN) * KK);
    float s = 0.f;
    #pragma unroll
    for (int c = 0; c < KK; c += 32) {
        float a = src[c + lane];
        s = fmaf(a, a, s);
    }
    #pragma unroll
    for (int o = 16; o; o >>= 1) s += __shfl_xor_sync(0xffffffffu, s, o);
    if (lane == 0) {
        if (gw < NN) g_xs[gw] = s; else g_ys[gw - NN] = s;
    }
}

__global__ void init_kernel() {
    int i = blockIdx.x * 256 + threadIdx.x;
    if (i < NN) g_v[i] = 0.f;
    if (i == 0) { g_bar_count = 0; g_bar_gen = 0; }
}

// ---------------------------------------------------------------------------
// C2[i][j] = (|x_i|^2 + |y_j|^2 - 2 x_i . y_j) * SCALEF  (fp32 FFMA GEMM)
__global__ __launch_bounds__(256) void gemm_kernel(const float* __restrict__ X,
                                                   const float* __restrict__ Y) {
    __shared__ float As[8][128];
    __shared__ float Bs[8][128];
    const int tid = threadIdx.x;
    const int bx = blockIdx.x;
    const int by = blockIdx.y;
    const int ar = tid >> 1;
    const int ak = (tid & 1) * 4;
    const int tx = tid & 15;
    const int ty = tid >> 4;

    const float* xp = X + (size_t)(by * 128 + ar) * KK + ak;
    const float* yp = Y + (size_t)(bx * 128 + ar) * KK + ak;

    float acc[8][8];
    #pragma unroll
    for (int i = 0; i < 8; ++i)
        #pragma unroll
        for (int j = 0; j < 8; ++j) acc[i][j] = 0.f;

    for (int kt = 0; kt < KK; kt += 8) {
        float4 av = *(const float4*)(xp + kt);
        float4 bv = *(const float4*)(yp + kt);
        __syncthreads();
        As[ak + 0][ar] = av.x; As[ak + 1][ar] = av.y;
        As[ak + 2][ar] = av.z; As[ak + 3][ar] = av.w;
        Bs[ak + 0][ar] = bv.x; Bs[ak + 1][ar] = bv.y;
        Bs[ak + 2][ar] = bv.z; Bs[ak + 3][ar] = bv.w;
        __syncthreads();
        #pragma unroll
        for (int k = 0; k < 8; ++k) {
            float a[8], b[8];
            *(float4*)(a)     = *(const float4*)&As[k][ty * 8];
            *(float4*)(a + 4) = *(const float4*)&As[k][ty * 8 + 4];
            *(float4*)(b)     = *(const float4*)&Bs[k][tx * 8];
            *(float4*)(b + 4) = *(const float4*)&Bs[k][tx * 8 + 4];
            #pragma unroll
            for (int i = 0; i < 8; ++i)
                #pragma unroll
                for (int j = 0; j < 8; ++j)
                    acc[i][j] = fmaf(a[i], b[j], acc[i][j]);
        }
    }

    const int gi0 = by * 128 + ty * 8;
    const int gj0 = bx * 128 + tx * 8;
    float yv[8];
    #pragma unroll
    for (int j = 0; j < 8; ++j) yv[j] = g_ys[gj0 + j];
    #pragma unroll
    for (int i = 0; i < 8; ++i) {
        float xs = g_xs[gi0 + i];
        float4 o0, o1;
        o0.x = (xs + yv[0] - 2.f * acc[i][0]) * SCALEF;
        o0.y = (xs + yv[1] - 2.f * acc[i][1]) * SCALEF;
        o0.z = (xs + yv[2] - 2.f * acc[i][2]) * SCALEF;
        o0.w = (xs + yv[3] - 2.f * acc[i][3]) * SCALEF;
        o1.x = (xs + yv[4] - 2.f * acc[i][4]) * SCALEF;
        o1.y = (xs + yv[5] - 2.f * acc[i][5]) * SCALEF;
        o1.z = (xs + yv[6] - 2.f * acc[i][6]) * SCALEF;
        o1.w = (xs + yv[7] - 2.f * acc[i][7]) * SCALEF;
        float* dst = g_C2 + (size_t)(gi0 + i) * NN + gj0;
        *(float4*)(dst)     = o0;
        *(float4*)(dst + 4) = o1;
    }
}

// ---------------------------------------------------------------------------
// Persistent fused Sinkhorn loop. One CTA per SM, software grid barriers.
// Phase A: per-CTA row sweep -> u for its rows + per-thread-register column
//          online (M,S) partials for its 8 owned columns (cols 4*tid+2048*k).
// Phase B: combine per-CTA column partials -> v.
__global__ __launch_bounds__(THREADS, 1) void sinkhorn_persistent(int NB, float* __restrict__ out) {
    const int tid = threadIdx.x;
    const int bid = blockIdx.x;
    const int lane = tid & 31;
    const int wid = tid >> 5;

    __shared__ float redA[4][16];
    __shared__ float redB[4][16];
    __shared__ float MSH[32][NBMAX + 1];
    __shared__ float SSH[32][NBMAX + 1];
    __shared__ float QM[32][4];
    __shared__ float QS[32][4];

    for (int it = 0; it < N_ITER; ++it) {
        // reload v (updated each iteration)
        float4 v0 = *(const float4*)&g_v[4 * tid];
        float4 v1 = *(const float4*)&g_v[4 * tid + 2048];
        float vv[8] = {v0.x, v0.y, v0.z, v0.w, v1.x, v1.y, v1.z, v1.w};

        // per-thread column online-LSE state (cols 4*tid + e + 2048*k)
        float Mc[8], Sc[8];
        #pragma unroll
        for (int k = 0; k < 8; ++k) { Mc[k] = NEG_BIG; Sc[k] = 0.f; }

        // ---- Phase A: row sweep, batches of 4 rows ----
        for (int r0 = bid; r0 < NN; r0 += 4 * NB) {
            bool valid[4];
            float Cv[4][8];
            #pragma unroll
            for (int r = 0; r < 4; ++r) {
                int row = r0 + r * NB;
                valid[r] = (row < NN);
                int ra = valid[r] ? row : bid;
                const float* p = g_C2 + (size_t)ra * NN + 4 * tid;
                float4 a = __ldg((const float4*)p);
                float4 b = __ldg((const float4*)(p + 2048));
                Cv[r][0] = a.x; Cv[r][1] = a.y; Cv[r][2] = a.z; Cv[r][3] = a.w;
                Cv[r][4] = b.x; Cv[r][5] = b.y; Cv[r][6] = b.z; Cv[r][7] = b.w;
            }
            // row max of t = v_j - C_ij
            float ml[4];
            #pragma unroll
            for (int r = 0; r < 4; ++r) {
                float m = vv[0] - Cv[r][0];
                #pragma unroll
                for (int k = 1; k < 8; ++k) m = fmaxf(m, vv[k] - Cv[r][k]);
                ml[r] = m;
            }
            #pragma unroll
            for (int o = 16; o; o >>= 1)
                #pragma unroll
                for (int r = 0; r < 4; ++r)
                    ml[r] = fmaxf(ml[r], __shfl_xor_sync(0xffffffffu, ml[r], o));
            __syncthreads();               // protect redA/redB from previous batch
            if (lane == 0) {
                #pragma unroll
                for (int r = 0; r < 4; ++r) redA[r][wid] = ml[r];
            }
            __syncthreads();
            float bm[4];
            #pragma unroll
            for (int r = 0; r < 4; ++r) {
                float m = redA[r][0];
                #pragma unroll
                for (int w = 1; w < 16; ++w) m = fmaxf(m, redA[r][w]);
                bm[r] = m;
            }
            // row exp-sums
            float sl[4];
            #pragma unroll
            for (int r = 0; r < 4; ++r) {
                float s = 0.f;
                #pragma unroll
                for (int k = 0; k < 8; ++k) s += ex2f(vv[k] - Cv[r][k] - bm[r]);
                sl[r] = s;
            }
            #pragma unroll
            for (int o = 16; o; o >>= 1)
                #pragma unroll
                for (int r = 0; r < 4; ++r)
                    sl[r] += __shfl_xor_sync(0xffffffffu, sl[r], o);
            if (lane == 0) {
                #pragma unroll
                for (int r = 0; r < 4; ++r) redB[r][wid] = sl[r];
            }
            __syncthreads();
            #pragma unroll
            for (int r = 0; r < 4; ++r) {
                float S = redB[r][0];
                #pragma unroll
                for (int w = 1; w < 16; ++w) S += redB[r][w];
                float rc = bm[r] + lg2f(S);        // rc = -u2_i
                if (tid == r && valid[r]) g_u[r0 + r * NB] = -rc;
                if (valid[r]) {
                    // column accumulate: E = u2_i - C2_ij = -Cv - rc
                    #pragma unroll
                    for (int k = 0; k < 8; ++k) {
                        float E = -Cv[r][k] - rc;
                        float Mo = Mc[k];
                        if (E > Mo) {                  // rare after first rows
                            Sc[k] *= ex2f(Mo - E);
                            Mc[k] = E; Mo = E;
                        }
                        Sc[k] += ex2f(E - Mo);
                    }
                }
            }
        }
        // write per-CTA column partials (coalesced float4)
        #pragma unroll
        for (int k = 0; k < 2; ++k) {
            float4 m4 = make_float4(Mc[4*k], Mc[4*k+1], Mc[4*k+2], Mc[4*k+3]);
            float4 s4 = make_float4(Sc[4*k], Sc[4*k+1], Sc[4*k+2], Sc[4*k+3]);
            *(float4*)&g_MP[(size_t)bid * NN + 4 * tid + 2048 * k] = m4;
            *(float4*)&g_SP[(size_t)bid * NN + 4 * tid + 2048 * k] = s4;
        }
        grid_sync(NB);

        // ---- Phase B: combine NB partials per column -> v ----
        for (int g = bid; g < NN / 32; g += NB) {
            int j0 = g << 5;
            for (int idx = tid; idx < NB * 32; idx += THREADS) {
                int c = idx & 31, b = idx >> 5;
                MSH[c][b] = g_MP[(size_t)b * NN + j0 + c];
                SSH[c][b] = g_SP[(size_t)b * NN + j0 + c];
            }
            __syncthreads();
            if (tid < 128) {
                int c = tid >> 2, q = tid & 3;
                float Ma = NEG_BIG, Sa = 0.f;
                for (int b = q; b < NB; b += 4) {
                    float Mb = MSH[c][b], Sb = SSH[c][b];
                    if (Mb > Ma) { Sa *= ex2f(Ma - Mb); Ma = Mb; }
                    Sa += Sb * ex2f(Mb - Ma);
                }
                QM[c][q] = Ma; QS[c][q] = Sa;
            }
            __syncthreads();
            if (tid < 32) {
                float Ma = QM[tid][0], Sa = QS[tid][0];
                #pragma unroll
                for (int q = 1; q < 4; ++q) {
                    float Mb = QM[tid][q], Sb = QS[tid][q];
                    if (Mb > Ma) { Sa *= ex2f(Ma - Mb); Ma = Mb; }
                    Sa += Sb * ex2f(Mb - Ma);
                }
                g_v[j0 + tid] = -(Ma + lg2f(Sa));
            }
            __syncthreads();
        }
        grid_sync(NB);
    }

    // ---- final cost: sum P*C / N ----
    {
        float4 v0 = *(const float4*)&g_v[4 * tid];
        float4 v1 = *(const float4*)&g_v[4 * tid + 2048];
        float vv[8] = {v0.x, v0.y, v0.z, v0.w, v1.x, v1.y, v1.z, v1.w};
        float acc = 0.f;
        for (int row = bid; row < NN; row += NB) {
            float u2 = g_u[row];
            const float* p = g_C2 + (size_t)row * NN + 4 * tid;
            float4 a = __ldg((const float4*)p);
            float4 b = __ldg((const float4*)(p + 2048));
            float Cv[8] = {a.x, a.y, a.z, a.w, b.x, b.y, b.z, b.w};
            #pragma unroll
            for (int k = 0; k < 8; ++k)
                acc = fmaf(ex2f(u2 + vv[k] - Cv[k]), Cv[k], acc);
        }
        #pragma unroll
        for (int o = 16; o; o >>= 1) acc += __shfl_xor_sync(0xffffffffu, acc, o);
        __syncthreads();
        if (lane == 0) redA[0][wid] = acc;
        __syncthreads();
        if (tid == 0) {
            float s = redA[0][0];
            #pragma unroll
            for (int w = 1; w < 16; ++w) s += redA[0][w];
            g_dpart[bid] = (double)s;
        }
        grid_sync(NB);
        if (bid == 0 && tid == 0) {
            double S = 0.0;
            for (int b = 0; b < NB; ++b) S += g_dpart[b];
            out[0] = (float)(S / ((double)SCALEF * (double)NN));
        }
    }
}

// ---------------------------------------------------------------------------
extern "C" void kernel_launch(void* const* d_in, const int* in_sizes, int n_in,
                              void* d_out, int out_size) {
    const float* x = (const float*)d_in[0];
    const float* y = (const float*)d_in[1];
    float* out = (float*)d_out;

    int dev = 0;
    cudaGetDevice(&dev);
    int sm = 148;
    cudaDeviceGetAttribute(&sm, cudaDevAttrMultiProcessorCount, dev);
    int NB = sm < NBMAX ? sm : NBMAX;

    sqnorm_kernel<<<1024, 256>>>(x, y);
    init_kernel<<<16, 256>>>();
    gemm_kernel<<<dim3(32, 32), 256>>>(x, y);
    sinkhorn_persistent<<<NB, THREADS>>>(NB, out);
}

// round 4
// speedup vs baseline: 1.0741x; 1.0741x over previous
#include <cuda_runtime.h>
#include <math.h>

// Sinkhorn distance, N=M=4096, D=256, EPS=0.1, 100 iterations.
// Persistent single-wave kernel, fused u+v update per iteration (C read once).
// All values pre-scaled by LOG2E/EPS so inner loops use exp2/log2 (MUFU).

#define NN 4096
#define KK 256
#define SCALEF 14.4269504088896340736f   // log2(e)/EPS
#define NEG_BIG (-1e30f)
#define THREADS 1024
#define NBMAX 160
#define NBS 161                          // odd stride, conflict-free smem
#define N_ITER 100

// ---- device scratch (no runtime allocations allowed) ----
__device__ __align__(16) float g_C2[(size_t)NN * NN];     // 64 MB: C * SCALEF
__device__ __align__(16) float g_u[NN];
__device__ __align__(16) float g_v[NN];
__device__ float g_xs[NN];
__device__ float g_ys[NN];
__device__ __align__(16) float g_MP[(size_t)NBMAX * NN];  // per-CTA column max partials
__device__ __align__(16) float g_SP[(size_t)NBMAX * NN];  // per-CTA column sum partials
__device__ double g_dpart[NBMAX];

__device__ unsigned g_bar_count;
__device__ volatile unsigned g_bar_gen;

__device__ __forceinline__ float ex2f(float x) {
    float r; asm("ex2.approx.ftz.f32 %0, %1;" : "=f"(r) : "f"(x)); return r;
}
__device__ __forceinline__ float lg2f(float x) {
    float r; asm("lg2.approx.ftz.f32 %0, %1;" : "=f"(r) : "f"(x)); return r;
}

__device__ __forceinline__ void grid_sync(int NB) {
    __syncthreads();
    if (threadIdx.x == 0) {
        unsigned gen = g_bar_gen;
        __threadfence();
        unsigned t = atomicAdd(&g_bar_count, 1u);
        if (t == (unsigned)(NB - 1)) {
            g_bar_count = 0;
            __threadfence();
            g_bar_gen = gen + 1;
        } else {
            while (g_bar_gen == gen) { }
        }
        __threadfence();
    }
    __syncthreads();
}

// ---------------------------------------------------------------------------
__global__ __launch_bounds__(256) void sqnorm_kernel(const float* __restrict__ X,
                                                     const float* __restrict__ Y) {
    int gw = (blockIdx.x * 256 + threadIdx.x) >> 5;
    int lane = threadIdx.x & 31;
    const float* src = (gw < NN) ? (X + (size_t)gw * KK) : (Y + (size_t)(gw - NN) * KK);
    float s = 0.f;
    #pragma unroll
    for (int c = 0; c < KK; c += 32) {
        float a = src[c + lane];
        s = fmaf(a, a, s);
    }
    #pragma unroll
    for (int o = 16; o; o >>= 1) s += __shfl_xor_sync(0xffffffffu, s, o);
    if (lane == 0) {
        if (gw < NN) g_xs[gw] = s; else g_ys[gw - NN] = s;
    }
}

__global__ void init_kernel() {
    int i = blockIdx.x * 256 + threadIdx.x;
    if (i < NN) g_v[i] = 0.f;
    if (i == 0) { g_bar_count = 0; g_bar_gen = 0; }
}

// ---------------------------------------------------------------------------
// C2[i][j] = (|x_i|^2 + |y_j|^2 - 2 x_i . y_j) * SCALEF  (fp32 FFMA GEMM)
__global__ __launch_bounds__(256) void gemm_kernel(const float* __restrict__ X,
                                                   const float* __restrict__ Y) {
    __shared__ float As[8][128];
    __shared__ float Bs[8][128];
    const int tid = threadIdx.x;
    const int bx = blockIdx.x;
    const int by = blockIdx.y;
    const int ar = tid >> 1;
    const int ak = (tid & 1) * 4;
    const int tx = tid & 15;
    const int ty = tid >> 4;

    const float* xp = X + (size_t)(by * 128 + ar) * KK + ak;
    const float* yp = Y + (size_t)(bx * 128 + ar) * KK + ak;

    float acc[8][8];
    #pragma unroll
    for (int i = 0; i < 8; ++i)
        #pragma unroll
        for (int j = 0; j < 8; ++j) acc[i][j] = 0.f;

    for (int kt = 0; kt < KK; kt += 8) {
        float4 av = *(const float4*)(xp + kt);
        float4 bv = *(const float4*)(yp + kt);
        __syncthreads();
        As[ak + 0][ar] = av.x; As[ak + 1][ar] = av.y;
        As[ak + 2][ar] = av.z; As[ak + 3][ar] = av.w;
        Bs[ak + 0][ar] = bv.x; Bs[ak + 1][ar] = bv.y;
        Bs[ak + 2][ar] = bv.z; Bs[ak + 3][ar] = bv.w;
        __syncthreads();
        #pragma unroll
        for (int k = 0; k < 8; ++k) {
            float a[8], b[8];
            *(float4*)(a)     = *(const float4*)&As[k][ty * 8];
            *(float4*)(a + 4) = *(const float4*)&As[k][ty * 8 + 4];
            *(float4*)(b)     = *(const float4*)&Bs[k][tx * 8];
            *(float4*)(b + 4) = *(const float4*)&Bs[k][tx * 8 + 4];
            #pragma unroll
            for (int i = 0; i < 8; ++i)
                #pragma unroll
                for (int j = 0; j < 8; ++j)
                    acc[i][j] = fmaf(a[i], b[j], acc[i][j]);
        }
    }

    const int gi0 = by * 128 + ty * 8;
    const int gj0 = bx * 128 + tx * 8;
    float yv[8];
    #pragma unroll
    for (int j = 0; j < 8; ++j) yv[j] = g_ys[gj0 + j];
    #pragma unroll
    for (int i = 0; i < 8; ++i) {
        float xs = g_xs[gi0 + i];
        float4 o0, o1;
        o0.x = (xs + yv[0] - 2.f * acc[i][0]) * SCALEF;
        o0.y = (xs + yv[1] - 2.f * acc[i][1]) * SCALEF;
        o0.z = (xs + yv[2] - 2.f * acc[i][2]) * SCALEF;
        o0.w = (xs + yv[3] - 2.f * acc[i][3]) * SCALEF;
        o1.x = (xs + yv[4] - 2.f * acc[i][4]) * SCALEF;
        o1.y = (xs + yv[5] - 2.f * acc[i][5]) * SCALEF;
        o1.z = (xs + yv[6] - 2.f * acc[i][6]) * SCALEF;
        o1.w = (xs + yv[7] - 2.f * acc[i][7]) * SCALEF;
        float* dst = g_C2 + (size_t)(gi0 + i) * NN + gj0;
        *(float4*)(dst)     = o0;
        *(float4*)(dst + 4) = o1;
    }
}

// ---------------------------------------------------------------------------
// Persistent fused Sinkhorn loop. 1024 threads/CTA, one CTA per SM.
// Phase A: batches of 4 rows. Per row: warp-local LSE partial (m,s) with the
//          warp max as shift; 4 combiner warps merge 32 partials; rc broadcast
//          via one smem scalar; then per-thread column online (Mc,Sc) update.
// Phase B: warp-per-column combine of NB partials -> v.
__global__ __launch_bounds__(THREADS, 1) void sinkhorn_persistent(int NB, float* __restrict__ out) {
    const int tid = threadIdx.x;
    const int bid = blockIdx.x;
    const int lane = tid & 31;
    const int wid = tid >> 5;

    __shared__ float sm_m[4][32];
    __shared__ float sm_s[4][32];
    __shared__ float sm_rc[4];
    __shared__ float MSH[32][NBS];
    __shared__ float SSH[32][NBS];
    __shared__ float sred[32];

    for (int it = 0; it < N_ITER; ++it) {
        float4 v4 = *(const float4*)&g_v[4 * tid];
        float vv[4] = {v4.x, v4.y, v4.z, v4.w};

        float Mc[4], Sc[4];
        #pragma unroll
        for (int k = 0; k < 4; ++k) { Mc[k] = NEG_BIG; Sc[k] = 0.f; }

        // ---- Phase A ----
        for (int r0 = bid; r0 < NN; r0 += 4 * NB) {
            float t[4][4];
            bool valid[4];
            #pragma unroll
            for (int r = 0; r < 4; ++r) {
                int row = r0 + r * NB;
                valid[r] = (row < NN);
                int ra = valid[r] ? row : bid;
                float4 c4 = *(const float4*)(g_C2 + (size_t)ra * NN + 4 * tid);
                t[r][0] = vv[0] - c4.x; t[r][1] = vv[1] - c4.y;
                t[r][2] = vv[2] - c4.z; t[r][3] = vv[3] - c4.w;
            }
            // warp-local (m,s) per row
            float mw[4], sw[4];
            #pragma unroll
            for (int r = 0; r < 4; ++r) {
                float m = fmaxf(fmaxf(t[r][0], t[r][1]), fmaxf(t[r][2], t[r][3]));
                #pragma unroll
                for (int o = 16; o; o >>= 1) m = fmaxf(m, __shfl_xor_sync(0xffffffffu, m, o));
                mw[r] = m;
            }
            #pragma unroll
            for (int r = 0; r < 4; ++r) {
                float s = ex2f(t[r][0] - mw[r]) + ex2f(t[r][1] - mw[r])
                        + ex2f(t[r][2] - mw[r]) + ex2f(t[r][3] - mw[r]);
                #pragma unroll
                for (int o = 16; o; o >>= 1) s += __shfl_xor_sync(0xffffffffu, s, o);
                sw[r] = s;
            }
            __syncthreads();   // sm_* reuse from previous batch fully consumed
            if (lane == 0) {
                #pragma unroll
                for (int r = 0; r < 4; ++r) { sm_m[r][wid] = mw[r]; sm_s[r][wid] = sw[r]; }
            }
            __syncthreads();
            if (wid < 4) {     // warp r combines its row's 32 partials
                float m = sm_m[wid][lane];
                float s = sm_s[wid][lane];
                #pragma unroll
                for (int o = 16; o; o >>= 1) {
                    float m2 = __shfl_xor_sync(0xffffffffu, m, o);
                    float s2 = __shfl_xor_sync(0xffffffffu, s, o);
                    float M = fmaxf(m, m2);
                    s = s * ex2f(m - M) + s2 * ex2f(m2 - M);
                    m = M;
                }
                if (lane == 0) {
                    float rc = m + lg2f(s);      // rc = -u2_row
                    sm_rc[wid] = rc;
                    int row = r0 + wid * NB;
                    if (row < NN) g_u[row] = -rc;
                }
            }
            __syncthreads();
            // column online update: E = u - C = t - v - rc
            #pragma unroll
            for (int r = 0; r < 4; ++r) {
                if (!valid[r]) continue;
                float rc = sm_rc[r];
                #pragma unroll
                for (int k = 0; k < 4; ++k) {
                    float E = t[r][k] - vv[k] - rc;
                    float arg = E - Mc[k];
                    if (arg > 0.f) {             // rare after first rows
                        Sc[k] = Sc[k] * ex2f(-arg) + 1.f;
                        Mc[k] = E;
                    } else {
                        Sc[k] += ex2f(arg);
                    }
                }
            }
        }
        *(float4*)&g_MP[(size_t)bid * NN + 4 * tid] = make_float4(Mc[0], Mc[1], Mc[2], Mc[3]);
        *(float4*)&g_SP[(size_t)bid * NN + 4 * tid] = make_float4(Sc[0], Sc[1], Sc[2], Sc[3]);
        grid_sync(NB);

        // ---- Phase B: combine NB partials per column -> v ----
        for (int g = bid; g < NN / 32; g += NB) {
            int j0 = g << 5;
            for (int idx = tid; idx < NB * 32; idx += THREADS) {
                int c = idx & 31, b = idx >> 5;
                MSH[c][b] = g_MP[(size_t)b * NN + j0 + c];
                SSH[c][b] = g_SP[(size_t)b * NN + j0 + c];
            }
            __syncthreads();
            {   // warp wid owns column j0+wid
                float Ma = NEG_BIG, Sa = 0.f;
                for (int b = lane; b < NB; b += 32) {
                    float Mb = MSH[wid][b], Sb = SSH[wid][b];
                    if (Mb > Ma) { Sa = Sa * ex2f(Ma - Mb) + Sb; Ma = Mb; }
                    else          { Sa += Sb * ex2f(Mb - Ma); }
                }
                #pragma unroll
                for (int o = 16; o; o >>= 1) {
                    float m2 = __shfl_xor_sync(0xffffffffu, Ma, o);
                    float s2 = __shfl_xor_sync(0xffffffffu, Sa, o);
                    float M = fmaxf(Ma, m2);
                    Sa = Sa * ex2f(Ma - M) + s2 * ex2f(m2 - M);
                    Ma = M;
                }
                if (lane == 0) g_v[j0 + wid] = -(Ma + lg2f(Sa));
            }
            __syncthreads();
        }
        grid_sync(NB);
    }

    // ---- final cost: sum P*C / N ----
    {
        float4 v4 = *(const float4*)&g_v[4 * tid];
        float vv[4] = {v4.x, v4.y, v4.z, v4.w};
        float acc = 0.f;
        for (int row = bid; row < NN; row += NB) {
            float u2 = g_u[row];
            float4 c4 = *(const float4*)(g_C2 + (size_t)row * NN + 4 * tid);
            float Cv[4] = {c4.x, c4.y, c4.z, c4.w};
            #pragma unroll
            for (int k = 0; k < 4; ++k)
                acc = fmaf(ex2f(u2 + vv[k] - Cv[k]), Cv[k], acc);
        }
        #pragma unroll
        for (int o = 16; o; o >>= 1) acc += __shfl_xor_sync(0xffffffffu, acc, o);
        __syncthreads();
        if (lane == 0) sred[wid] = acc;
        __syncthreads();
        if (wid == 0) {
            float s = sred[lane];
            #pragma unroll
            for (int o = 16; o; o >>= 1) s += __shfl_xor_sync(0xffffffffu, s, o);
            if (lane == 0) g_dpart[bid] = (double)s;
        }
        grid_sync(NB);
        if (bid == 0 && tid == 0) {
            double S = 0.0;
            for (int b = 0; b < NB; ++b) S += g_dpart[b];
            out[0] = (float)(S / ((double)SCALEF * (double)NN));
        }
    }
}

// ---------------------------------------------------------------------------
extern "C" void kernel_launch(void* const* d_in, const int* in_sizes, int n_in,
                              void* d_out, int out_size) {
    const float* x = (const float*)d_in[0];
    const float* y = (const float*)d_in[1];
    float* out = (float*)d_out;

    int dev = 0;
    cudaGetDevice(&dev);
    int sm = 148;
    cudaDeviceGetAttribute(&sm, cudaDevAttrMultiProcessorCount, dev);
    int NB = sm < NBMAX ? sm : NBMAX;

    sqnorm_kernel<<<1024, 256>>>(x, y);
    init_kernel<<<16, 256>>>();
    gemm_kernel<<<dim3(32, 32), 256>>>(x, y);
    sinkhorn_persistent<<<NB, THREADS>>>(NB, out);
}

// round 5
// speedup vs baseline: 1.4140x; 1.3164x over previous
#include <cuda_runtime.h>
#include <math.h>

// Sinkhorn distance, N=M=4096, D=256, EPS=0.1, 100 iterations.
// Persistent single-wave kernel; split u/v passes with warp-local reductions
// only (no __syncthreads in element loops). Log2-scaled throughout.

#define NN 4096
#define KK 256
#define SCALEF 14.4269504088896340736f   // log2(e)/EPS
#define NEG_BIG (-1e30f)
#define THREADS 1024
#define NBMAX 160
#define N_ITER 100

__device__ __align__(16) float g_C2[(size_t)NN * NN];     // 64 MB: C * SCALEF
__device__ __align__(16) float g_u[NN];
__device__ __align__(16) float g_v[NN];
__device__ float g_xs[NN];
__device__ float g_ys[NN];
__device__ double g_dpart[NBMAX];

__device__ unsigned g_bar_count;
__device__ volatile unsigned g_bar_gen;

__device__ __forceinline__ float ex2f(float x) {
    float r; asm("ex2.approx.ftz.f32 %0, %1;" : "=f"(r) : "f"(x)); return r;
}
__device__ __forceinline__ float lg2f(float x) {
    float r; asm("lg2.approx.ftz.f32 %0, %1;" : "=f"(r) : "f"(x)); return r;
}

__device__ __forceinline__ void grid_sync(int NB) {
    __syncthreads();
    if (threadIdx.x == 0) {
        unsigned gen = g_bar_gen;
        __threadfence();
        unsigned t = atomicAdd(&g_bar_count, 1u);
        if (t == (unsigned)(NB - 1)) {
            g_bar_count = 0;
            __threadfence();
            g_bar_gen = gen + 1;
        } else {
            while (g_bar_gen == gen) { }
        }
        __threadfence();
    }
    __syncthreads();
}

// online-LSE pairwise merge of (m,s) across the warp (5 shfl steps)
__device__ __forceinline__ void warp_lse_merge(float& m, float& s) {
    #pragma unroll
    for (int o = 16; o; o >>= 1) {
        float m2 = __shfl_xor_sync(0xffffffffu, m, o);
        float s2 = __shfl_xor_sync(0xffffffffu, s, o);
        float M = fmaxf(m, m2);
        s = s * ex2f(m - M) + s2 * ex2f(m2 - M);
        m = M;
    }
}

// ---------------------------------------------------------------------------
__global__ __launch_bounds__(256) void sqnorm_kernel(const float* __restrict__ X,
                                                     const float* __restrict__ Y) {
    int gw = (blockIdx.x * 256 + threadIdx.x) >> 5;
    int lane = threadIdx.x & 31;
    const float* src = (gw < NN) ? (X + (size_t)gw * KK) : (Y + (size_t)(gw - NN) * KK);
    float s = 0.f;
    #pragma unroll
    for (int c = 0; c < KK; c += 32) {
        float a = src[c + lane];
        s = fmaf(a, a, s);
    }
    #pragma unroll
    for (int o = 16; o; o >>= 1) s += __shfl_xor_sync(0xffffffffu, s, o);
    if (lane == 0) {
        if (gw < NN) g_xs[gw] = s; else g_ys[gw - NN] = s;
    }
}

__global__ void init_kernel() {
    int i = blockIdx.x * 256 + threadIdx.x;
    if (i < NN) g_v[i] = 0.f;
    if (i == 0) { g_bar_count = 0; g_bar_gen = 0; }
}

// ---------------------------------------------------------------------------
// C2[i][j] = (|x_i|^2 + |y_j|^2 - 2 x_i . y_j) * SCALEF  (fp32 FFMA GEMM)
__global__ __launch_bounds__(256) void gemm_kernel(const float* __restrict__ X,
                                                   const float* __restrict__ Y) {
    __shared__ float As[8][128];
    __shared__ float Bs[8][128];
    const int tid = threadIdx.x;
    const int bx = blockIdx.x;
    const int by = blockIdx.y;
    const int ar = tid >> 1;
    const int ak = (tid & 1) * 4;
    const int tx = tid & 15;
    const int ty = tid >> 4;

    const float* xp = X + (size_t)(by * 128 + ar) * KK + ak;
    const float* yp = Y + (size_t)(bx * 128 + ar) * KK + ak;

    float acc[8][8];
    #pragma unroll
    for (int i = 0; i < 8; ++i)
        #pragma unroll
        for (int j = 0; j < 8; ++j) acc[i][j] = 0.f;

    for (int kt = 0; kt < KK; kt += 8) {
        float4 av = *(const float4*)(xp + kt);
        float4 bv = *(const float4*)(yp + kt);
        __syncthreads();
        As[ak + 0][ar] = av.x; As[ak + 1][ar] = av.y;
        As[ak + 2][ar] = av.z; As[ak + 3][ar] = av.w;
        Bs[ak + 0][ar] = bv.x; Bs[ak + 1][ar] = bv.y;
        Bs[ak + 2][ar] = bv.z; Bs[ak + 3][ar] = bv.w;
        __syncthreads();
        #pragma unroll
        for (int k = 0; k < 8; ++k) {
            float a[8], b[8];
            *(float4*)(a)     = *(const float4*)&As[k][ty * 8];
            *(float4*)(a + 4) = *(const float4*)&As[k][ty * 8 + 4];
            *(float4*)(b)     = *(const float4*)&Bs[k][tx * 8];
            *(float4*)(b + 4) = *(const float4*)&Bs[k][tx * 8 + 4];
            #pragma unroll
            for (int i = 0; i < 8; ++i)
                #pragma unroll
                for (int j = 0; j < 8; ++j)
                    acc[i][j] = fmaf(a[i], b[j], acc[i][j]);
        }
    }

    const int gi0 = by * 128 + ty * 8;
    const int gj0 = bx * 128 + tx * 8;
    float yv[8];
    #pragma unroll
    for (int j = 0; j < 8; ++j) yv[j] = g_ys[gj0 + j];
    #pragma unroll
    for (int i = 0; i < 8; ++i) {
        float xs = g_xs[gi0 + i];
        float4 o0, o1;
        o0.x = (xs + yv[0] - 2.f * acc[i][0]) * SCALEF;
        o0.y = (xs + yv[1] - 2.f * acc[i][1]) * SCALEF;
        o0.z = (xs + yv[2] - 2.f * acc[i][2]) * SCALEF;
        o0.w = (xs + yv[3] - 2.f * acc[i][3]) * SCALEF;
        o1.x = (xs + yv[4] - 2.f * acc[i][4]) * SCALEF;
        o1.y = (xs + yv[5] - 2.f * acc[i][5]) * SCALEF;
        o1.z = (xs + yv[6] - 2.f * acc[i][6]) * SCALEF;
        o1.w = (xs + yv[7] - 2.f * acc[i][7]) * SCALEF;
        float* dst = g_C2 + (size_t)(gi0 + i) * NN + gj0;
        *(float4*)(dst)     = o0;
        *(float4*)(dst + 4) = o1;
    }
}

// ---------------------------------------------------------------------------
__global__ __launch_bounds__(THREADS, 1) void sinkhorn_persistent(int NB, float* __restrict__ out) {
    const int tid = threadIdx.x;
    const int bid = blockIdx.x;
    const int lane = tid & 31;
    const int wid = tid >> 5;

    __shared__ float svec[NN];          // 16 KB: v (u-pass) / u (v-pass) cache
    __shared__ float sm_m[32][33];
    __shared__ float sm_s[32][33];
    __shared__ float sred[32];

    for (int it = 0; it < N_ITER; ++it) {
        // ---- u-pass: warp-per-row, warp-local reduction only ----
        for (int i = tid; i < NN; i += THREADS) svec[i] = g_v[i];
        __syncthreads();

        for (int row = bid + wid * NB; row < NN; row += 32 * NB) {
            const float* Crow = g_C2 + (size_t)row * NN;
            float m = NEG_BIG, s = 0.f;
            #pragma unroll 4
            for (int c0 = 0; c0 < NN; c0 += 128) {
                int c = c0 + lane * 4;
                float4 C4 = __ldg((const float4*)(Crow + c));
                float4 V4 = *(const float4*)&svec[c];
                float t0 = V4.x - C4.x, t1 = V4.y - C4.y;
                float t2 = V4.z - C4.z, t3 = V4.w - C4.w;
                float mc = fmaxf(fmaxf(t0, t1), fmaxf(t2, t3));
                if (mc > m) { s *= ex2f(m - mc); m = mc; }
                s += ex2f(t0 - m) + ex2f(t1 - m) + ex2f(t2 - m) + ex2f(t3 - m);
            }
            warp_lse_merge(m, s);
            float u2 = -(m + lg2f(s));
            if (lane == 0) g_u[row] = u2;
        }
        grid_sync(NB);

        // ---- v-pass: CTA bid owns 32 columns; coalesced column sweep ----
        for (int i = tid; i < NN; i += THREADS) svec[i] = g_u[i];
        __syncthreads();
        for (int g = bid; g < NN / 32; g += NB) {
            const int c = lane;                 // column within group
            const int r = wid;                  // row stratum 0..31
            const int col = (g << 5) + c;
            float m = NEG_BIG, s = 0.f;
            for (int q0 = 0; q0 < NN; q0 += 512) {
                const float* p = g_C2 + (size_t)(q0 + r) * NN + col;
                const float* up = &svec[q0 + r];
                float t[16];
                #pragma unroll
                for (int k = 0; k < 16; ++k)
                    t[k] = up[k << 5] - __ldg(p + ((size_t)k << 5) * NN);
                float mc = t[0];
                #pragma unroll
                for (int k = 1; k < 16; ++k) mc = fmaxf(mc, t[k]);
                if (mc > m) { s *= ex2f(m - mc); m = mc; }
                #pragma unroll
                for (int k = 0; k < 16; ++k) s += ex2f(t[k] - m);
            }
            sm_m[r][c] = m;
            sm_s[r][c] = s;
            __syncthreads();
            {   // warp wid merges the 32 strata of column wid
                float mm = sm_m[lane][wid];
                float ss = sm_s[lane][wid];
                warp_lse_merge(mm, ss);
                if (lane == 0) g_v[(g << 5) + wid] = -(mm + lg2f(ss));
            }
            __syncthreads();
        }
        grid_sync(NB);
    }

    // ---- final cost: sum P*C / N  (warp-per-row) ----
    {
        for (int i = tid; i < NN; i += THREADS) svec[i] = g_v[i];
        __syncthreads();
        float acc = 0.f;
        for (int row = bid + wid * NB; row < NN; row += 32 * NB) {
            const float u2 = g_u[row];
            const float* Crow = g_C2 + (size_t)row * NN;
            #pragma unroll 4
            for (int c0 = 0; c0 < NN; c0 += 128) {
                int cc = c0 + lane * 4;
                float4 C4 = __ldg((const float4*)(Crow + cc));
                float4 V4 = *(const float4*)&svec[cc];
                acc = fmaf(ex2f(u2 + V4.x - C4.x), C4.x, acc);
                acc = fmaf(ex2f(u2 + V4.y - C4.y), C4.y, acc);
                acc = fmaf(ex2f(u2 + V4.z - C4.z), C4.z, acc);
                acc = fmaf(ex2f(u2 + V4.w - C4.w), C4.w, acc);
            }
        }
        #pragma unroll
        for (int o = 16; o; o >>= 1) acc += __shfl_xor_sync(0xffffffffu, acc, o);
        __syncthreads();
        if (lane == 0) sred[wid] = acc;
        __syncthreads();
        if (wid == 0) {
            float s = sred[lane];
            #pragma unroll
            for (int o = 16; o; o >>= 1) s += __shfl_xor_sync(0xffffffffu, s, o);
            if (lane == 0) g_dpart[bid] = (double)s;
        }
        grid_sync(NB);
        if (bid == 0 && tid == 0) {
            double S = 0.0;
            for (int b = 0; b < NB; ++b) S += g_dpart[b];
            out[0] = (float)(S / ((double)SCALEF * (double)NN));
        }
    }
}

// ---------------------------------------------------------------------------
extern "C" void kernel_launch(void* const* d_in, const int* in_sizes, int n_in,
                              void* d_out, int out_size) {
    const float* x = (const float*)d_in[0];
    const float* y = (const float*)d_in[1];
    float* out = (float*)d_out;

    int dev = 0;
    cudaGetDevice(&dev);
    int sm = 148;
    cudaDeviceGetAttribute(&sm, cudaDevAttrMultiProcessorCount, dev);
    int NB = sm < NBMAX ? sm : NBMAX;

    sqnorm_kernel<<<1024, 256>>>(x, y);
    init_kernel<<<16, 256>>>();
    gemm_kernel<<<dim3(32, 32), 256>>>(x, y);
    sinkhorn_persistent<<<NB, THREADS>>>(NB, out);
}